// round 2
// baseline (speedup 1.0000x reference)
#include <cuda_runtime.h>

// Problem constants
#define IDIM   32
#define MDIM   16
#define DDIM   48          // IDIM + MDIM combined projection
#define NQ     64
#define NP1    65          // NQ + 1 (assignment_prob last dim)
#define QDIM   256
#define NBT    8           // B*T
#define PIX_PER_BT 65536   // V*H*W = 4*128*128
#define NPIX   524288      // NBT * PIX_PER_BT
#define TPB    256

// Scratch for projected queries: [bt][q][d], d in [0,48) = inst(32) ++ motion(16)
__device__ float g_qi[NBT * NQ * DDIM];

// ---------------------------------------------------------------------------
// Kernel 1: query_inst / query_motion projection (tiny: 8 * 64 * 48 dots of 256)
// ---------------------------------------------------------------------------
__global__ void qproj_kernel(const float* __restrict__ qf,
                             const float* __restrict__ Wi,
                             const float* __restrict__ bi,
                             const float* __restrict__ Wm,
                             const float* __restrict__ bm) {
    int bt = blockIdx.x;
    const float* qbase = qf + bt * NQ * QDIM;

    // Cache this bt's query_feat rows in smem (64*256 f32 = 64 KB)
    extern __shared__ float s_qf[];
    for (int i = threadIdx.x; i < NQ * QDIM; i += blockDim.x)
        s_qf[i] = qbase[i];
    __syncthreads();

    for (int idx = threadIdx.x; idx < NQ * DDIM; idx += blockDim.x) {
        int q = idx / DDIM;
        int d = idx % DDIM;
        const float* qrow = s_qf + q * QDIM;
        float acc;
        if (d < IDIM) {
            acc = bi[d];
            #pragma unroll 8
            for (int k = 0; k < QDIM; k++) acc += qrow[k] * Wi[k * IDIM + d];
        } else {
            int dm = d - IDIM;
            acc = bm[dm];
            #pragma unroll 8
            for (int k = 0; k < QDIM; k++) acc += qrow[k] * Wm[k * MDIM + dm];
        }
        g_qi[bt * NQ * DDIM + idx] = acc;
    }
}

// ---------------------------------------------------------------------------
// Kernel 2: per-pixel pooling + fused refine
// Block = 256 threads = 256 consecutive pixels (all within one bt).
// smem: s_ap[256*65] staged coalesced, s_qi[64*48] broadcast matrix.
// ---------------------------------------------------------------------------
__global__ void __launch_bounds__(TPB)
entity_kernel(const float* __restrict__ ia,
              const float* __restrict__ mc,
              const float* __restrict__ ap,
              const int*   __restrict__ aq,
              float*       __restrict__ out) {
    extern __shared__ float sm[];
    float* s_ap = sm;                  // 256*65 = 16640 floats
    float* s_qi = sm + TPB * NP1;      // 64*48  =  3072 floats

    const int tid = threadIdx.x;
    const int p0  = blockIdx.x * TPB;          // first pixel of block (< 2^20)
    const int bt  = p0 / PIX_PER_BT;           // whole block in one bt (65536 % 256 == 0)

    // Load projection matrix (3072 floats, coalesced, 12/thread)
    const float* gq = g_qi + bt * (NQ * DDIM);
    #pragma unroll
    for (int i = tid; i < NQ * DDIM; i += TPB) s_qi[i] = gq[i];

    // Stage assignment_prob block: one contiguous 66560B chunk, float4-coalesced.
    // p0*65*4 bytes is 16B-aligned since 256*65*4 = 66560 ≡ 0 (mod 16).
    {
        const float4* apv = (const float4*)(ap + (size_t)p0 * NP1);
        float4* s4 = (float4*)s_ap;
        const int NV = TPB * NP1 / 4;  // 4160
        #pragma unroll
        for (int i = tid; i < NV; i += TPB) s4[i] = apv[i];
    }
    __syncthreads();

    const int p = p0 + tid;
    const float* myap = s_ap + tid * NP1;   // stride 65 words: odd -> conflict-free

    float bg   = myap[0];
    float fsum = 0.f;
    float acc[DDIM];
    #pragma unroll
    for (int d = 0; d < DDIM; d++) acc[d] = 0.f;

    #pragma unroll 4
    for (int q = 0; q < NQ; q++) {
        float f = myap[1 + q];
        fsum += f;
        const float* qi = s_qi + q * DDIM;   // broadcast across warp, 16B-aligned rows
        #pragma unroll
        for (int d = 0; d < DDIM; d++) acc[d] += f * qi[d];
    }

    const float scale = (1.f - bg) / fmaxf(fsum, 1e-6f);

    // ---- outputs (float32 concat: [entity | inst | motion]) ----
    // entity_id
    out[p] = (float)aq[p];

    // inst: ia[p*32 ..] + scale*acc[0..32)
    {
        const float4* iav = (const float4*)(ia + (size_t)p * IDIM);
        float4* ov = (float4*)(out + (size_t)NPIX + (size_t)p * IDIM);
        #pragma unroll
        for (int i = 0; i < IDIM / 4; i++) {
            float4 v = iav[i];
            v.x += scale * acc[i * 4 + 0];
            v.y += scale * acc[i * 4 + 1];
            v.z += scale * acc[i * 4 + 2];
            v.w += scale * acc[i * 4 + 3];
            ov[i] = v;
        }
    }

    // motion: mc[p*16 ..] + scale*acc[32..48)
    {
        const float4* mcv = (const float4*)(mc + (size_t)p * MDIM);
        float4* ov = (float4*)(out + (size_t)NPIX + (size_t)NPIX * IDIM + (size_t)p * MDIM);
        #pragma unroll
        for (int i = 0; i < MDIM / 4; i++) {
            float4 v = mcv[i];
            v.x += scale * acc[IDIM + i * 4 + 0];
            v.y += scale * acc[IDIM + i * 4 + 1];
            v.z += scale * acc[IDIM + i * 4 + 2];
            v.w += scale * acc[IDIM + i * 4 + 3];
            ov[i] = v;
        }
    }
}

// ---------------------------------------------------------------------------
extern "C" void kernel_launch(void* const* d_in, const int* in_sizes, int n_in,
                              void* d_out, int out_size) {
    const float* ia = (const float*)d_in[0];  // instance_affinity
    const float* mc = (const float*)d_in[1];  // motion_code
    const float* qf = (const float*)d_in[2];  // query_feat
    const float* ap = (const float*)d_in[3];  // assignment_prob
    const int*   aq = (const int*)  d_in[4];  // assigned_query (int32: jax x64 off)
    const float* Wi = (const float*)d_in[5];
    const float* bi = (const float*)d_in[6];
    const float* Wm = (const float*)d_in[7];
    const float* bm = (const float*)d_in[8];

    const int qproj_smem  = NQ * QDIM * (int)sizeof(float);                 // 64 KB
    const int entity_smem = (TPB * NP1 + NQ * DDIM) * (int)sizeof(float);   // 78848 B

    cudaFuncSetAttribute(qproj_kernel,
                         cudaFuncAttributeMaxDynamicSharedMemorySize, qproj_smem);
    cudaFuncSetAttribute(entity_kernel,
                         cudaFuncAttributeMaxDynamicSharedMemorySize, entity_smem);

    qproj_kernel<<<NBT, 256, qproj_smem>>>(qf, Wi, bi, Wm, bm);
    entity_kernel<<<NPIX / TPB, TPB, entity_smem>>>(ia, mc, ap, aq, (float*)d_out);
}

// round 5
// speedup vs baseline: 1.6063x; 1.6063x over previous
#include <cuda_runtime.h>

// Problem constants
#define IDIM   32
#define MDIM   16
#define DDIM   48          // IDIM + MDIM combined projection
#define NQ     64
#define NP1    65          // NQ + 1 (assignment_prob last dim)
#define QDIM   256
#define NBT    8           // B*T
#define PIX_PER_BT 65536   // V*H*W = 4*128*128
#define NPIX   524288      // NBT * PIX_PER_BT
#define TPB    256
#define ACC_STRIDE 52      // padded row stride for s_acc (bank-conflict-free, 16B-aligned)

// Scratch for projected queries: [bt][q][d], d in [0,48) = inst(32) ++ motion(16)
__device__ __align__(16) float g_qi[NBT * NQ * DDIM];

// ---------------------------------------------------------------------------
// Kernel 1: query projection. One block per (bt, q) row -> 512 blocks.
// ---------------------------------------------------------------------------
__global__ void __launch_bounds__(64)
qproj_kernel(const float* __restrict__ qf,
             const float* __restrict__ Wi,
             const float* __restrict__ bi,
             const float* __restrict__ Wm,
             const float* __restrict__ bm) {
    const int r = blockIdx.x;            // r = bt*NQ + q, matches qf row layout
    __shared__ float s_q[QDIM];
    const float* qrow = qf + (size_t)r * QDIM;
    for (int i = threadIdx.x; i < QDIM; i += 64) s_q[i] = qrow[i];
    __syncthreads();

    const int d = threadIdx.x;
    if (d < DDIM) {
        float acc;
        if (d < IDIM) {
            acc = bi[d];
            #pragma unroll 8
            for (int k = 0; k < QDIM; k++) acc += s_q[k] * Wi[k * IDIM + d];
        } else {
            const int dm = d - IDIM;
            acc = bm[dm];
            #pragma unroll 8
            for (int k = 0; k < QDIM; k++) acc += s_q[k] * Wm[k * MDIM + dm];
        }
        g_qi[r * DDIM + d] = acc;
    }
}

// ---------------------------------------------------------------------------
// Kernel 2: per-pixel pooling + fused refine.
// 256 threads = 256 pixels. fg pooling in packed f32x2 FMAs.
// Epilogue routed through smem so all global I/O is coalesced.
// ---------------------------------------------------------------------------
__global__ void __launch_bounds__(TPB)
entity_kernel(const float* __restrict__ ia,
              const float* __restrict__ mc,
              const float* __restrict__ ap,
              const int*   __restrict__ aq,
              float*       __restrict__ out) {
    extern __shared__ float sm[];
    float* s_qi = sm;                    // 3072 floats
    float* s_ap = sm + NQ * DDIM;        // 256*65 = 16640 floats (reused as s_acc)

    const int tid = threadIdx.x;
    const int p0  = blockIdx.x * TPB;
    const int bt  = blockIdx.x >> 8;     // 256 blocks per bt

    // Stage projection matrix (768 float4, coalesced)
    {
        const float4* gq = (const float4*)(g_qi + bt * (NQ * DDIM));
        float4* sq4 = (float4*)s_qi;
        #pragma unroll
        for (int i = tid; i < NQ * DDIM / 4; i += TPB) sq4[i] = gq[i];
    }
    // Stage assignment_prob: one contiguous 66560B chunk, float4-coalesced
    {
        const float4* apv = (const float4*)(ap + (size_t)p0 * NP1);
        float4* s4 = (float4*)s_ap;
        #pragma unroll
        for (int i = tid; i < TPB * NP1 / 4; i += TPB) s4[i] = apv[i];
    }
    __syncthreads();

    const float* myap = s_ap + tid * NP1;    // odd stride -> conflict-free scalar LDS
    const float bg = myap[0];
    const float* fgp = myap + 1;

    float fsum = 0.f;
    unsigned long long acc[DDIM / 2];        // 24 packed f32x2 accumulators
    #pragma unroll
    for (int j = 0; j < DDIM / 2; j++) acc[j] = 0ull;

    #pragma unroll 4
    for (int q = 0; q < NQ; q++) {
        const float f = fgp[q];
        fsum += f;
        unsigned int fb = __float_as_uint(f);
        unsigned long long f2;
        asm("mov.b64 %0, {%1, %1};" : "=l"(f2) : "r"(fb));
        const ulonglong2* qv = (const ulonglong2*)(s_qi + q * DDIM); // 16B-aligned
        #pragma unroll
        for (int j = 0; j < DDIM / 4; j++) {        // 12 LDS.128 -> 24 f32x2 pairs
            ulonglong2 v = qv[j];
            asm("fma.rn.f32x2 %0, %1, %2, %0;" : "+l"(acc[2*j  ]) : "l"(f2), "l"(v.x));
            asm("fma.rn.f32x2 %0, %1, %2, %0;" : "+l"(acc[2*j+1]) : "l"(f2), "l"(v.y));
        }
    }

    const float scale = (1.f - bg) / fmaxf(fsum, 1e-6f);

    __syncthreads();                 // everyone done reading s_ap
    float* s_acc = s_ap;             // reuse: 256 rows x 52 floats = 13312 < 16640
    {
        float4* sa4 = (float4*)s_acc;
        #pragma unroll
        for (int j = 0; j < DDIM / 4; j++) {
            unsigned int l0, h0, l1, h1;
            asm("mov.b64 {%0, %1}, %2;" : "=r"(l0), "=r"(h0) : "l"(acc[2*j]));
            asm("mov.b64 {%0, %1}, %2;" : "=r"(l1), "=r"(h1) : "l"(acc[2*j+1]));
            float4 w;
            w.x = scale * __uint_as_float(l0);
            w.y = scale * __uint_as_float(h0);
            w.z = scale * __uint_as_float(l1);
            w.w = scale * __uint_as_float(h1);
            sa4[tid * (ACC_STRIDE / 4) + j] = w;   // stride 52 floats: conflict-free
        }
    }
    __syncthreads();

    // ---- fully coalesced epilogue ----
    // entity_id
    out[p0 + tid] = (float)aq[p0 + tid];

    const float4* sa4 = (const float4*)s_acc;

    // inst: out[NPIX + p*32 + i] = ia[p*32 + i] + s_acc[p_local][i]
    {
        const float4* ia4 = (const float4*)(ia + (size_t)p0 * IDIM);
        float4* o4 = (float4*)(out + (size_t)NPIX + (size_t)p0 * IDIM);
        #pragma unroll
        for (int it = 0; it < TPB * IDIM / 4 / TPB; it++) {   // 8 iters
            const int i  = tid + it * TPB;                    // 0..2047
            const int j  = i >> 3;                            // local pixel
            const int d4 = i & 7;                             // float4 within inst
            float4 v = ia4[i];
            float4 a = sa4[j * (ACC_STRIDE / 4) + d4];
            v.x += a.x; v.y += a.y; v.z += a.z; v.w += a.w;
            o4[i] = v;
        }
    }
    // motion: out[NPIX + NPIX*32 + p*16 + i] = mc[p*16 + i] + s_acc[p_local][32+i]
    {
        const float4* mc4 = (const float4*)(mc + (size_t)p0 * MDIM);
        float4* o4 = (float4*)(out + (size_t)NPIX + (size_t)NPIX * IDIM + (size_t)p0 * MDIM);
        #pragma unroll
        for (int it = 0; it < TPB * MDIM / 4 / TPB; it++) {   // 4 iters
            const int i  = tid + it * TPB;                    // 0..1023
            const int j  = i >> 2;
            const int d4 = i & 3;
            float4 v = mc4[i];
            float4 a = sa4[j * (ACC_STRIDE / 4) + (IDIM / 4) + d4];
            v.x += a.x; v.y += a.y; v.z += a.z; v.w += a.w;
            o4[i] = v;
        }
    }
}

// ---------------------------------------------------------------------------
extern "C" void kernel_launch(void* const* d_in, const int* in_sizes, int n_in,
                              void* d_out, int out_size) {
    const float* ia = (const float*)d_in[0];
    const float* mc = (const float*)d_in[1];
    const float* qf = (const float*)d_in[2];
    const float* ap = (const float*)d_in[3];
    const int*   aq = (const int*)  d_in[4];
    const float* Wi = (const float*)d_in[5];
    const float* bi = (const float*)d_in[6];
    const float* Wm = (const float*)d_in[7];
    const float* bm = (const float*)d_in[8];

    const int entity_smem = (NQ * DDIM + TPB * NP1) * (int)sizeof(float);  // 78848 B
    cudaFuncSetAttribute(entity_kernel,
                         cudaFuncAttributeMaxDynamicSharedMemorySize, entity_smem);

    qproj_kernel<<<NBT * NQ, 64>>>(qf, Wi, bi, Wm, bm);
    entity_kernel<<<NPIX / TPB, TPB, entity_smem>>>(ia, mc, ap, aq, (float*)d_out);
}

// round 6
// speedup vs baseline: 1.8560x; 1.1554x over previous
#include <cuda_runtime.h>
#include <cstdint>

// Problem constants
#define IDIM   32
#define MDIM   16
#define DDIM   48          // IDIM + MDIM combined projection
#define NQ     64
#define NP1    65          // NQ + 1
#define QDIM   256
#define NBT    8           // B*T
#define PIX_PER_BT 65536
#define NPIX   524288
#define TPB    256
#define PPB    512         // pixels per block (2 per thread)
#define NBLK   (NPIX / PPB)          // 1024
#define ACC_STRIDE 52      // padded s_acc row stride (floats), 16B aligned

#define QI_BYTES  (NQ * DDIM * 4)          // 12288
#define AP_BYTES  (PPB * NP1 * 4)          // 133120
#define SMEM_BYTES (QI_BYTES + AP_BYTES)   // 145408

// Projected queries: [bt][q][d]
__device__ __align__(16) float g_qi[NBT * NQ * DDIM];

// ---------------------------------------------------------------------------
// Kernel 1: query projection. One block per (bt, q) row.
// ---------------------------------------------------------------------------
__global__ void __launch_bounds__(64)
qproj_kernel(const float* __restrict__ qf,
             const float* __restrict__ Wi,
             const float* __restrict__ bi,
             const float* __restrict__ Wm,
             const float* __restrict__ bm) {
    const int r = blockIdx.x;
    __shared__ float s_q[QDIM];
    const float* qrow = qf + (size_t)r * QDIM;
    for (int i = threadIdx.x; i < QDIM; i += 64) s_q[i] = qrow[i];
    __syncthreads();

    const int d = threadIdx.x;
    if (d < DDIM) {
        float acc;
        if (d < IDIM) {
            acc = bi[d];
            #pragma unroll 8
            for (int k = 0; k < QDIM; k++) acc += s_q[k] * Wi[k * IDIM + d];
        } else {
            const int dm = d - IDIM;
            acc = bm[dm];
            #pragma unroll 8
            for (int k = 0; k < QDIM; k++) acc += s_q[k] * Wm[k * MDIM + dm];
        }
        g_qi[r * DDIM + d] = acc;
    }
}

// ---------------------------------------------------------------------------
// Kernel 2: pooling + fused refine. 256 threads handle 512 pixels (t, t+256).
// Staging via cp.async.bulk; pooling in packed f32x2 FMAs; coalesced epilogue.
// ---------------------------------------------------------------------------
__global__ void __launch_bounds__(TPB)
entity_kernel(const float* __restrict__ ia,
              const float* __restrict__ mc,
              const float* __restrict__ ap,
              const int*   __restrict__ aq,
              float*       __restrict__ out) {
    extern __shared__ float sm[];
    float* s_qi = sm;                    // 3072 floats
    float* s_ap = sm + NQ * DDIM;        // 512*65 = 33280 floats (reused as s_acc)
    __shared__ __align__(8) unsigned long long mbar;

    const int tid = threadIdx.x;
    const int p0  = blockIdx.x * PPB;
    const int bt  = blockIdx.x >> 7;     // 128 blocks per bt

    // ---- bulk-stage qi + ap ----
    unsigned int mb  = (unsigned int)__cvta_generic_to_shared(&mbar);
    unsigned int sqi = (unsigned int)__cvta_generic_to_shared(s_qi);
    unsigned int sap = (unsigned int)__cvta_generic_to_shared(s_ap);

    if (tid == 0) {
        asm volatile("mbarrier.init.shared.b64 [%0], %1;" :: "r"(mb), "r"(1) : "memory");
        asm volatile("mbarrier.arrive.expect_tx.shared.b64 _, [%0], %1;"
                     :: "r"(mb), "r"((unsigned)SMEM_BYTES) : "memory");
    }
    __syncthreads();
    if (tid == 0) {
        const void* src_qi = (const void*)(g_qi + bt * (NQ * DDIM));
        const void* src_ap = (const void*)(ap + (size_t)p0 * NP1);
        asm volatile("cp.async.bulk.shared::cta.global.mbarrier::complete_tx::bytes "
                     "[%0], [%1], %2, [%3];"
                     :: "r"(sqi), "l"(src_qi), "r"((unsigned)QI_BYTES), "r"(mb) : "memory");
        asm volatile("cp.async.bulk.shared::cta.global.mbarrier::complete_tx::bytes "
                     "[%0], [%1], %2, [%3];"
                     :: "r"(sap), "l"(src_ap), "r"((unsigned)AP_BYTES), "r"(mb) : "memory");
    }
    // all threads wait (phase 0), acquire
    {
        unsigned int done;
        asm volatile("{\n\t.reg .pred p;\n\t"
                     "mbarrier.try_wait.parity.acquire.cta.shared::cta.b64 p, [%1], 0;\n\t"
                     "selp.b32 %0, 1, 0, p;\n\t}"
                     : "=r"(done) : "r"(mb) : "memory");
        while (!done) {
            asm volatile("{\n\t.reg .pred p;\n\t"
                         "mbarrier.try_wait.parity.acquire.cta.shared::cta.b64 p, [%1], 0, 0x989680;\n\t"
                         "selp.b32 %0, 1, 0, p;\n\t}"
                         : "=r"(done) : "r"(mb) : "memory");
        }
    }

    // ---- pooling: 2 pixels per thread (t and t+256) ----
    const float* rowA = s_ap + tid * NP1;            // bank-conflict-free (odd stride)
    const float* rowB = rowA + 256 * NP1;

    const float bgA = rowA[0];
    const float bgB = rowB[0];
    const float* fgA = rowA + 1;
    const float* fgB = rowB + 1;

    float fsA = 0.f, fsB = 0.f;
    unsigned long long accA[DDIM / 2], accB[DDIM / 2];
    #pragma unroll
    for (int j = 0; j < DDIM / 2; j++) { accA[j] = 0ull; accB[j] = 0ull; }

    #pragma unroll 4
    for (int q = 0; q < NQ; q++) {
        const float fA = fgA[q];
        const float fB = fgB[q];
        fsA += fA; fsB += fB;
        unsigned long long f2A, f2B;
        {
            unsigned int ba = __float_as_uint(fA), bb = __float_as_uint(fB);
            asm("mov.b64 %0, {%1, %1};" : "=l"(f2A) : "r"(ba));
            asm("mov.b64 %0, {%1, %1};" : "=l"(f2B) : "r"(bb));
        }
        const ulonglong2* qv = (const ulonglong2*)(s_qi + q * DDIM);  // broadcast
        #pragma unroll
        for (int j = 0; j < DDIM / 4; j++) {
            ulonglong2 v = qv[j];
            asm("fma.rn.f32x2 %0, %1, %2, %0;" : "+l"(accA[2*j  ]) : "l"(f2A), "l"(v.x));
            asm("fma.rn.f32x2 %0, %1, %2, %0;" : "+l"(accA[2*j+1]) : "l"(f2A), "l"(v.y));
            asm("fma.rn.f32x2 %0, %1, %2, %0;" : "+l"(accB[2*j  ]) : "l"(f2B), "l"(v.x));
            asm("fma.rn.f32x2 %0, %1, %2, %0;" : "+l"(accB[2*j+1]) : "l"(f2B), "l"(v.y));
        }
    }

    const float scA = (1.f - bgA) / fmaxf(fsA, 1e-6f);
    const float scB = (1.f - bgB) / fmaxf(fsB, 1e-6f);

    __syncthreads();                 // everyone done reading s_ap
    float* s_acc = s_ap;             // 512 rows x 52 floats = 26624 < 33280
    {
        float4* sa4 = (float4*)s_acc;
        #pragma unroll
        for (int j = 0; j < DDIM / 4; j++) {
            unsigned int l0, h0, l1, h1;
            float4 w;
            asm("mov.b64 {%0, %1}, %2;" : "=r"(l0), "=r"(h0) : "l"(accA[2*j]));
            asm("mov.b64 {%0, %1}, %2;" : "=r"(l1), "=r"(h1) : "l"(accA[2*j+1]));
            w.x = scA * __uint_as_float(l0);
            w.y = scA * __uint_as_float(h0);
            w.z = scA * __uint_as_float(l1);
            w.w = scA * __uint_as_float(h1);
            sa4[tid * (ACC_STRIDE / 4) + j] = w;
            asm("mov.b64 {%0, %1}, %2;" : "=r"(l0), "=r"(h0) : "l"(accB[2*j]));
            asm("mov.b64 {%0, %1}, %2;" : "=r"(l1), "=r"(h1) : "l"(accB[2*j+1]));
            w.x = scB * __uint_as_float(l0);
            w.y = scB * __uint_as_float(h0);
            w.z = scB * __uint_as_float(l1);
            w.w = scB * __uint_as_float(h1);
            sa4[(tid + 256) * (ACC_STRIDE / 4) + j] = w;
        }
    }
    __syncthreads();

    // ---- fully coalesced epilogue ----
    out[p0 + tid]       = (float)aq[p0 + tid];
    out[p0 + tid + 256] = (float)aq[p0 + tid + 256];

    const float4* sa4 = (const float4*)s_acc;

    // inst: PPB*IDIM/4 = 4096 float4 -> 16 iters
    {
        const float4* ia4 = (const float4*)(ia + (size_t)p0 * IDIM);
        float4* o4 = (float4*)(out + (size_t)NPIX + (size_t)p0 * IDIM);
        #pragma unroll
        for (int it = 0; it < PPB * IDIM / 4 / TPB; it++) {
            const int i  = tid + it * TPB;
            const int j  = i >> 3;          // local pixel 0..511
            const int d4 = i & 7;
            float4 v = ia4[i];
            float4 a = sa4[j * (ACC_STRIDE / 4) + d4];
            v.x += a.x; v.y += a.y; v.z += a.z; v.w += a.w;
            o4[i] = v;
        }
    }
    // motion: PPB*MDIM/4 = 2048 float4 -> 8 iters
    {
        const float4* mc4 = (const float4*)(mc + (size_t)p0 * MDIM);
        float4* o4 = (float4*)(out + (size_t)NPIX + (size_t)NPIX * IDIM + (size_t)p0 * MDIM);
        #pragma unroll
        for (int it = 0; it < PPB * MDIM / 4 / TPB; it++) {
            const int i  = tid + it * TPB;
            const int j  = i >> 2;
            const int d4 = i & 3;
            float4 v = mc4[i];
            float4 a = sa4[j * (ACC_STRIDE / 4) + (IDIM / 4) + d4];
            v.x += a.x; v.y += a.y; v.z += a.z; v.w += a.w;
            o4[i] = v;
        }
    }
}

// ---------------------------------------------------------------------------
extern "C" void kernel_launch(void* const* d_in, const int* in_sizes, int n_in,
                              void* d_out, int out_size) {
    const float* ia = (const float*)d_in[0];
    const float* mc = (const float*)d_in[1];
    const float* qf = (const float*)d_in[2];
    const float* ap = (const float*)d_in[3];
    const int*   aq = (const int*)  d_in[4];
    const float* Wi = (const float*)d_in[5];
    const float* bi = (const float*)d_in[6];
    const float* Wm = (const float*)d_in[7];
    const float* bm = (const float*)d_in[8];

    cudaFuncSetAttribute(entity_kernel,
                         cudaFuncAttributeMaxDynamicSharedMemorySize, SMEM_BYTES);

    qproj_kernel<<<NBT * NQ, 64>>>(qf, Wi, bi, Wm, bm);
    entity_kernel<<<NBLK, TPB, SMEM_BYTES>>>(ia, mc, ap, aq, (float*)d_out);
}

// round 8
// speedup vs baseline: 2.8814x; 1.5525x over previous
#include <cuda_runtime.h>
#include <cstdint>

// Problem constants
#define IDIM   32
#define MDIM   16
#define DDIM   48
#define NQ     64
#define NP1    65
#define QDIM   256
#define NBT    8
#define NPIX   524288
#define TPB    128
#define PPB    128
#define NBLK   (NPIX / PPB)   // 4096
#define ACC_STRIDE 52

// MMA tiling: D[128,56] = A[128,64] @ B[64,56]; m16n8k8 tf32, 3xTF32 emulation.
#define NI 7                  // 56 / 8  (cols 0..47 = data, 48 = ones, 49..55 = 0)
#define KI 8                  // 64 / 8

// B fragment image: [pass(2)][ni(7)][ki(8)][lane(32)][slot(2)] floats
#define BF_FLOATS (2 * NI * KI * 64)       // 7168
#define BF_BYTES  (BF_FLOATS * 4)          // 28672

#define AP_BYTES  (PPB * NP1 * 4)          // 33280
#define S_B_OFF   0
#define S_AP_OFF  BF_BYTES                 // 28672 (1KB aligned)
#define SMEM_BYTES (S_AP_OFF + AP_BYTES)   // 61952 -> 3 blocks/SM

__device__ __align__(16) float g_Bf[NBT * BF_FLOATS];

__device__ __forceinline__ uint32_t f2tf32(float x) {
    uint32_t r;
    asm("cvt.rna.tf32.f32 %0, %1;" : "=r"(r) : "f"(x));
    return r;
}

// ---------------------------------------------------------------------------
// Kernel 1: query projection -> B fragment image (hi/lo split, ones column).
// Block r = bt*64 + q; thread d in [0,64).
// ---------------------------------------------------------------------------
__global__ void __launch_bounds__(64)
qproj_kernel(const float* __restrict__ qf,
             const float* __restrict__ Wi,
             const float* __restrict__ bi,
             const float* __restrict__ Wm,
             const float* __restrict__ bm) {
    const int r  = blockIdx.x;
    const int bt = r >> 6;
    const int q  = r & 63;
    __shared__ float s_q[QDIM];
    const float* qrow = qf + (size_t)r * QDIM;
    for (int i = threadIdx.x; i < QDIM; i += 64) s_q[i] = qrow[i];
    __syncthreads();

    const int d = threadIdx.x;
    if (d >= 56) return;

    float val;
    if (d < IDIM) {
        val = bi[d];
        #pragma unroll 8
        for (int k = 0; k < QDIM; k++) val += s_q[k] * Wi[k * IDIM + d];
    } else if (d < DDIM) {
        const int dm = d - IDIM;
        val = bm[dm];
        #pragma unroll 8
        for (int k = 0; k < QDIM; k++) val += s_q[k] * Wm[k * MDIM + dm];
    } else {
        val = (d == DDIM) ? 1.0f : 0.0f;
    }

    const uint32_t hi = f2tf32(val);
    const float    lf = val - __uint_as_float(hi);
    const uint32_t lo = f2tf32(lf);

    // Fragment indices: B[k=q][n=d]; b0 at (k=tig, n=g), b1 at (k=tig+4, n=g)
    const int ni   = d >> 3;
    const int g    = d & 7;
    const int ki   = q >> 3;
    const int kl   = q & 7;
    const int tig  = kl & 3;
    const int slot = kl >> 2;
    const int lane = g * 4 + tig;

    float* dst = g_Bf + bt * BF_FLOATS;
    dst[((0 * NI + ni) * KI + ki) * 64 + lane * 2 + slot] = __uint_as_float(hi);
    dst[((1 * NI + ni) * KI + ki) * 64 + lane * 2 + slot] = __uint_as_float(lo);
}

// ---------------------------------------------------------------------------
// Kernel 2: 3xTF32 mma.sync pooling + fused refine. 128 threads / 128 pixels.
// warp w covers rows [w*32, w*32+32) (mi = 0,1 -> 16-row tiles).
// ---------------------------------------------------------------------------
__global__ void __launch_bounds__(TPB)
entity_kernel(const float* __restrict__ ia,
              const float* __restrict__ mc,
              const float* __restrict__ ap,
              const int*   __restrict__ aq,
              float*       __restrict__ out) {
    extern __shared__ __align__(1024) char smem[];
    float* s_B  = (float*)(smem + S_B_OFF);
    float* s_ap = (float*)(smem + S_AP_OFF);
    __shared__ __align__(8) unsigned long long tma_bar;

    const int tid  = threadIdx.x;
    const int w    = tid >> 5;
    const int lane = tid & 31;
    const int g    = lane >> 2;
    const int tig  = lane & 3;
    const int p0   = blockIdx.x * PPB;
    const int bt   = blockIdx.x >> 9;        // 512 blocks per bt

    unsigned int mb     = (unsigned int)__cvta_generic_to_shared(&tma_bar);
    unsigned int s_base = (unsigned int)__cvta_generic_to_shared(smem);

    if (tid == 0) {
        asm volatile("mbarrier.init.shared.b64 [%0], 1;" :: "r"(mb) : "memory");
        asm volatile("mbarrier.arrive.expect_tx.shared.b64 _, [%0], %1;"
                     :: "r"(mb), "r"((unsigned)(AP_BYTES + BF_BYTES)) : "memory");
    }
    __syncthreads();
    if (tid == 0) {
        const void* src_ap = (const void*)(ap + (size_t)p0 * NP1);
        const void* src_b  = (const void*)(g_Bf + bt * BF_FLOATS);
        asm volatile("cp.async.bulk.shared::cta.global.mbarrier::complete_tx::bytes "
                     "[%0], [%1], %2, [%3];"
                     :: "r"(s_base + S_AP_OFF), "l"(src_ap), "r"((unsigned)AP_BYTES),
                        "r"(mb) : "memory");
        asm volatile("cp.async.bulk.shared::cta.global.mbarrier::complete_tx::bytes "
                     "[%0], [%1], %2, [%3];"
                     :: "r"(s_base + S_B_OFF), "l"(src_b), "r"((unsigned)BF_BYTES),
                        "r"(mb) : "memory");
    }
    // wait (parity 0, acquire)
    {
        unsigned int done;
        asm volatile("{\n\t.reg .pred p;\n\t"
                     "mbarrier.try_wait.parity.acquire.cta.shared::cta.b64 p, [%1], 0;\n\t"
                     "selp.b32 %0, 1, 0, p;\n\t}" : "=r"(done) : "r"(mb) : "memory");
        while (!done) {
            asm volatile("{\n\t.reg .pred p;\n\t"
                         "mbarrier.try_wait.parity.acquire.cta.shared::cta.b64 p, [%1], 0, 0x989680;\n\t"
                         "selp.b32 %0, 1, 0, p;\n\t}" : "=r"(done) : "r"(mb) : "memory");
        }
    }

    // ---- 3xTF32 MMA mainloop ----
    float c[2][NI][4];
    #pragma unroll
    for (int mi = 0; mi < 2; mi++)
        #pragma unroll
        for (int ni = 0; ni < NI; ni++)
            #pragma unroll
            for (int j = 0; j < 4; j++) c[mi][ni][j] = 0.f;

    const int r_base = w * 32 + g;

    #pragma unroll
    for (int ki = 0; ki < KI; ki++) {
        uint32_t ah[2][4], al[2][4];
        #pragma unroll
        for (int mi = 0; mi < 2; mi++) {
            const int r0 = r_base + mi * 16;
            const int q0 = ki * 8 + tig;
            #pragma unroll
            for (int j = 0; j < 4; j++) {
                const int rr = r0 + ((j & 1) ? 8 : 0);
                const int qq = q0 + ((j & 2) ? 4 : 0);
                const float x = s_ap[rr * NP1 + 1 + qq];
                ah[mi][j] = f2tf32(x);
                al[mi][j] = f2tf32(x - __uint_as_float(ah[mi][j]));
            }
        }
        #pragma unroll
        for (int ni = 0; ni < NI; ni++) {
            const float2 bhv = *(const float2*)(s_B + ((0 * NI + ni) * KI + ki) * 64 + lane * 2);
            const float2 blv = *(const float2*)(s_B + ((1 * NI + ni) * KI + ki) * 64 + lane * 2);
            const uint32_t bh0 = __float_as_uint(bhv.x), bh1 = __float_as_uint(bhv.y);
            const uint32_t bl0 = __float_as_uint(blv.x), bl1 = __float_as_uint(blv.y);
            #pragma unroll
            for (int mi = 0; mi < 2; mi++) {
                asm("mma.sync.aligned.m16n8k8.row.col.f32.tf32.tf32.f32 "
                    "{%0,%1,%2,%3}, {%4,%5,%6,%7}, {%8,%9}, {%0,%1,%2,%3};"
                    : "+f"(c[mi][ni][0]), "+f"(c[mi][ni][1]), "+f"(c[mi][ni][2]), "+f"(c[mi][ni][3])
                    : "r"(ah[mi][0]), "r"(ah[mi][1]), "r"(ah[mi][2]), "r"(ah[mi][3]),
                      "r"(bh0), "r"(bh1));
                asm("mma.sync.aligned.m16n8k8.row.col.f32.tf32.tf32.f32 "
                    "{%0,%1,%2,%3}, {%4,%5,%6,%7}, {%8,%9}, {%0,%1,%2,%3};"
                    : "+f"(c[mi][ni][0]), "+f"(c[mi][ni][1]), "+f"(c[mi][ni][2]), "+f"(c[mi][ni][3])
                    : "r"(al[mi][0]), "r"(al[mi][1]), "r"(al[mi][2]), "r"(al[mi][3]),
                      "r"(bh0), "r"(bh1));
                asm("mma.sync.aligned.m16n8k8.row.col.f32.tf32.tf32.f32 "
                    "{%0,%1,%2,%3}, {%4,%5,%6,%7}, {%8,%9}, {%0,%1,%2,%3};"
                    : "+f"(c[mi][ni][0]), "+f"(c[mi][ni][1]), "+f"(c[mi][ni][2]), "+f"(c[mi][ni][3])
                    : "r"(ah[mi][0]), "r"(ah[mi][1]), "r"(ah[mi][2]), "r"(ah[mi][3]),
                      "r"(bl0), "r"(bl1));
            }
        }
    }

    // ---- per-row scale: fsum = D[:,48] (ni=6, tig=0 threads hold it) ----
    float sc0[2], sc1[2];
    #pragma unroll
    for (int mi = 0; mi < 2; mi++) {
        const int r0 = r_base + mi * 16;
        const float fs0 = __shfl_sync(0xffffffffu, c[mi][6][0], lane & ~3);
        const float fs1 = __shfl_sync(0xffffffffu, c[mi][6][2], lane & ~3);
        const float bg0 = s_ap[r0 * NP1];
        const float bg1 = s_ap[(r0 + 8) * NP1];
        sc0[mi] = (1.f - bg0) / fmaxf(fs0, 1e-6f);
        sc1[mi] = (1.f - bg1) / fmaxf(fs1, 1e-6f);
    }

    __syncthreads();                  // all warps done reading s_B
    float* s_acc = s_B;               // 128 x 52 floats = 26624 <= 28672
    #pragma unroll
    for (int mi = 0; mi < 2; mi++) {
        const int r0 = r_base + mi * 16;
        #pragma unroll
        for (int ni = 0; ni < 6; ni++) {   // cols 0..47 only
            const int col = ni * 8 + 2 * tig;
            float2 v0, v1;
            v0.x = sc0[mi] * c[mi][ni][0];
            v0.y = sc0[mi] * c[mi][ni][1];
            v1.x = sc1[mi] * c[mi][ni][2];
            v1.y = sc1[mi] * c[mi][ni][3];
            *(float2*)(s_acc + r0 * ACC_STRIDE + col)       = v0;
            *(float2*)(s_acc + (r0 + 8) * ACC_STRIDE + col) = v1;
        }
    }
    __syncthreads();

    // ---- fully coalesced epilogue ----
    out[p0 + tid] = (float)aq[p0 + tid];

    const float4* sa4 = (const float4*)s_acc;
    {
        const float4* ia4 = (const float4*)(ia + (size_t)p0 * IDIM);
        float4* o4 = (float4*)(out + (size_t)NPIX + (size_t)p0 * IDIM);
        #pragma unroll
        for (int it = 0; it < PPB * IDIM / 4 / TPB; it++) {   // 8
            const int i  = tid + it * TPB;
            const int j  = i >> 3;
            const int d4 = i & 7;
            float4 v = ia4[i];
            float4 a = sa4[j * (ACC_STRIDE / 4) + d4];
            v.x += a.x; v.y += a.y; v.z += a.z; v.w += a.w;
            o4[i] = v;
        }
    }
    {
        const float4* mc4 = (const float4*)(mc + (size_t)p0 * MDIM);
        float4* o4 = (float4*)(out + (size_t)NPIX + (size_t)NPIX * IDIM + (size_t)p0 * MDIM);
        #pragma unroll
        for (int it = 0; it < PPB * MDIM / 4 / TPB; it++) {   // 4
            const int i  = tid + it * TPB;
            const int j  = i >> 2;
            const int d4 = i & 3;
            float4 v = mc4[i];
            float4 a = sa4[j * (ACC_STRIDE / 4) + (IDIM / 4) + d4];
            v.x += a.x; v.y += a.y; v.z += a.z; v.w += a.w;
            o4[i] = v;
        }
    }
}

// ---------------------------------------------------------------------------
extern "C" void kernel_launch(void* const* d_in, const int* in_sizes, int n_in,
                              void* d_out, int out_size) {
    const float* ia = (const float*)d_in[0];
    const float* mc = (const float*)d_in[1];
    const float* qf = (const float*)d_in[2];
    const float* ap = (const float*)d_in[3];
    const int*   aq = (const int*)  d_in[4];
    const float* Wi = (const float*)d_in[5];
    const float* bi = (const float*)d_in[6];
    const float* Wm = (const float*)d_in[7];
    const float* bm = (const float*)d_in[8];

    cudaFuncSetAttribute(entity_kernel,
                         cudaFuncAttributeMaxDynamicSharedMemorySize, SMEM_BYTES);

    qproj_kernel<<<NBT * NQ, 64>>>(qf, Wi, bi, Wm, bm);
    entity_kernel<<<NBLK, TPB, SMEM_BYTES>>>(ia, mc, ap, aq, (float*)d_out);
}

// round 9
// speedup vs baseline: 3.0557x; 1.0605x over previous
#include <cuda_runtime.h>
#include <cstdint>

// Problem constants
#define IDIM   32
#define MDIM   16
#define DDIM   48
#define NQ     64
#define NP1    65
#define QDIM   256
#define NBT    8
#define NPIX   524288
#define TPB    128
#define PPB    128
#define NBLK   (NPIX / PPB)   // 4096
#define ACC_STRIDE 52

// MMA tiling: D[128,48] = A[128,64] @ B[64,48]; m16n8k8 tf32.
// A single-pass tf32; B split hi+lo (2 MMAs per tile). fsum computed scalar.
#define NI 6                  // 48 / 8
#define KI 8                  // 64 / 8

// B fragment image: [pass(2)][ni(6)][ki(8)][lane(32)][slot(2)] floats
#define BF_FLOATS (2 * NI * KI * 64)       // 6144
#define BF_BYTES  (BF_FLOATS * 4)          // 24576

#define AP_BYTES  (PPB * NP1 * 4)          // 33280
#define S_B_OFF   0
#define S_AP_OFF  BF_BYTES                 // 24576
#define SMEM_BYTES (S_AP_OFF + AP_BYTES)   // 57856 -> 3 blocks/SM

__device__ __align__(16) float g_Bf[NBT * BF_FLOATS];

__device__ __forceinline__ uint32_t f2tf32(float x) {
    uint32_t r;
    asm("cvt.rna.tf32.f32 %0, %1;" : "=r"(r) : "f"(x));
    return r;
}

// ---------------------------------------------------------------------------
// Kernel 1: query projection -> B fragment image (hi/lo split).
// Block r = bt*64 + q; thread d in [0,64), active d < 48.
// ---------------------------------------------------------------------------
__global__ void __launch_bounds__(64)
qproj_kernel(const float* __restrict__ qf,
             const float* __restrict__ Wi,
             const float* __restrict__ bi,
             const float* __restrict__ Wm,
             const float* __restrict__ bm) {
    const int r  = blockIdx.x;
    const int bt = r >> 6;
    const int q  = r & 63;
    __shared__ float s_q[QDIM];
    const float* qrow = qf + (size_t)r * QDIM;
    for (int i = threadIdx.x; i < QDIM; i += 64) s_q[i] = qrow[i];
    __syncthreads();

    const int d = threadIdx.x;
    if (d >= DDIM) return;

    float val;
    if (d < IDIM) {
        val = bi[d];
        #pragma unroll 8
        for (int k = 0; k < QDIM; k++) val += s_q[k] * Wi[k * IDIM + d];
    } else {
        const int dm = d - IDIM;
        val = bm[dm];
        #pragma unroll 8
        for (int k = 0; k < QDIM; k++) val += s_q[k] * Wm[k * MDIM + dm];
    }

    const uint32_t hi = f2tf32(val);
    const float    lf = val - __uint_as_float(hi);
    const uint32_t lo = f2tf32(lf);

    // Fragment indices: B[k=q][n=d]; b0 at (k=tig, n=g), b1 at (k=tig+4, n=g)
    const int ni   = d >> 3;
    const int g    = d & 7;
    const int ki   = q >> 3;
    const int kl   = q & 7;
    const int tig  = kl & 3;
    const int slot = kl >> 2;
    const int lane = g * 4 + tig;

    float* dst = g_Bf + bt * BF_FLOATS;
    dst[((0 * NI + ni) * KI + ki) * 64 + lane * 2 + slot] = __uint_as_float(hi);
    dst[((1 * NI + ni) * KI + ki) * 64 + lane * 2 + slot] = __uint_as_float(lo);
}

// ---------------------------------------------------------------------------
// Kernel 2: tf32 mma.sync pooling (A-hi x {B-hi,B-lo}) + fused refine.
// 128 threads / 128 pixels; warp w covers rows [w*32, w*32+32).
// ---------------------------------------------------------------------------
__global__ void __launch_bounds__(TPB)
entity_kernel(const float* __restrict__ ia,
              const float* __restrict__ mc,
              const float* __restrict__ ap,
              const int*   __restrict__ aq,
              float*       __restrict__ out) {
    extern __shared__ __align__(1024) char smem[];
    float* s_B  = (float*)(smem + S_B_OFF);
    float* s_ap = (float*)(smem + S_AP_OFF);
    __shared__ __align__(8) unsigned long long tma_bar;

    const int tid  = threadIdx.x;
    const int w    = tid >> 5;
    const int lane = tid & 31;
    const int g    = lane >> 2;
    const int tig  = lane & 3;
    const int p0   = blockIdx.x * PPB;
    const int bt   = blockIdx.x >> 9;        // 512 blocks per bt

    unsigned int mb     = (unsigned int)__cvta_generic_to_shared(&tma_bar);
    unsigned int s_base = (unsigned int)__cvta_generic_to_shared(smem);

    if (tid == 0) {
        asm volatile("mbarrier.init.shared.b64 [%0], 1;" :: "r"(mb) : "memory");
        asm volatile("mbarrier.arrive.expect_tx.shared.b64 _, [%0], %1;"
                     :: "r"(mb), "r"((unsigned)(AP_BYTES + BF_BYTES)) : "memory");
    }
    __syncthreads();
    if (tid == 0) {
        const void* src_ap = (const void*)(ap + (size_t)p0 * NP1);
        const void* src_b  = (const void*)(g_Bf + bt * BF_FLOATS);
        asm volatile("cp.async.bulk.shared::cta.global.mbarrier::complete_tx::bytes "
                     "[%0], [%1], %2, [%3];"
                     :: "r"(s_base + S_AP_OFF), "l"(src_ap), "r"((unsigned)AP_BYTES),
                        "r"(mb) : "memory");
        asm volatile("cp.async.bulk.shared::cta.global.mbarrier::complete_tx::bytes "
                     "[%0], [%1], %2, [%3];"
                     :: "r"(s_base + S_B_OFF), "l"(src_b), "r"((unsigned)BF_BYTES),
                        "r"(mb) : "memory");
    }
    // wait (parity 0, acquire)
    {
        unsigned int done;
        asm volatile("{\n\t.reg .pred p;\n\t"
                     "mbarrier.try_wait.parity.acquire.cta.shared::cta.b64 p, [%1], 0;\n\t"
                     "selp.b32 %0, 1, 0, p;\n\t}" : "=r"(done) : "r"(mb) : "memory");
        while (!done) {
            asm volatile("{\n\t.reg .pred p;\n\t"
                         "mbarrier.try_wait.parity.acquire.cta.shared::cta.b64 p, [%1], 0, 0x989680;\n\t"
                         "selp.b32 %0, 1, 0, p;\n\t}" : "=r"(done) : "r"(mb) : "memory");
        }
    }

    // ---- MMA mainloop: A single-pass tf32, B hi+lo ----
    float c[2][NI][4];
    #pragma unroll
    for (int mi = 0; mi < 2; mi++)
        #pragma unroll
        for (int ni = 0; ni < NI; ni++)
            #pragma unroll
            for (int j = 0; j < 4; j++) c[mi][ni][j] = 0.f;

    const int r_base = w * 32 + g;

    // scalar fsum partials: [mi][row-half (j&1)]
    float fs[2][2] = {{0.f, 0.f}, {0.f, 0.f}};

    #pragma unroll
    for (int ki = 0; ki < KI; ki++) {
        uint32_t ah[2][4];
        #pragma unroll
        for (int mi = 0; mi < 2; mi++) {
            const int r0 = r_base + mi * 16;
            const int q0 = ki * 8 + tig;
            #pragma unroll
            for (int j = 0; j < 4; j++) {
                const int rr = r0 + ((j & 1) ? 8 : 0);
                const int qq = q0 + ((j & 2) ? 4 : 0);
                const float x = s_ap[rr * NP1 + 1 + qq];
                fs[mi][j & 1] += x;
                ah[mi][j] = f2tf32(x);
            }
        }
        #pragma unroll
        for (int ni = 0; ni < NI; ni++) {
            const float2 bhv = *(const float2*)(s_B + ((0 * NI + ni) * KI + ki) * 64 + lane * 2);
            const float2 blv = *(const float2*)(s_B + ((1 * NI + ni) * KI + ki) * 64 + lane * 2);
            const uint32_t bh0 = __float_as_uint(bhv.x), bh1 = __float_as_uint(bhv.y);
            const uint32_t bl0 = __float_as_uint(blv.x), bl1 = __float_as_uint(blv.y);
            #pragma unroll
            for (int mi = 0; mi < 2; mi++) {
                asm("mma.sync.aligned.m16n8k8.row.col.f32.tf32.tf32.f32 "
                    "{%0,%1,%2,%3}, {%4,%5,%6,%7}, {%8,%9}, {%0,%1,%2,%3};"
                    : "+f"(c[mi][ni][0]), "+f"(c[mi][ni][1]), "+f"(c[mi][ni][2]), "+f"(c[mi][ni][3])
                    : "r"(ah[mi][0]), "r"(ah[mi][1]), "r"(ah[mi][2]), "r"(ah[mi][3]),
                      "r"(bh0), "r"(bh1));
                asm("mma.sync.aligned.m16n8k8.row.col.f32.tf32.tf32.f32 "
                    "{%0,%1,%2,%3}, {%4,%5,%6,%7}, {%8,%9}, {%0,%1,%2,%3};"
                    : "+f"(c[mi][ni][0]), "+f"(c[mi][ni][1]), "+f"(c[mi][ni][2]), "+f"(c[mi][ni][3])
                    : "r"(ah[mi][0]), "r"(ah[mi][1]), "r"(ah[mi][2]), "r"(ah[mi][3]),
                      "r"(bl0), "r"(bl1));
            }
        }
    }

    // ---- reduce fsum over the 4-lane tig group (lanes g*4 + 0..3) ----
    #pragma unroll
    for (int mi = 0; mi < 2; mi++) {
        #pragma unroll
        for (int h = 0; h < 2; h++) {
            fs[mi][h] += __shfl_xor_sync(0xffffffffu, fs[mi][h], 1);
            fs[mi][h] += __shfl_xor_sync(0xffffffffu, fs[mi][h], 2);
        }
    }

    float sc0[2], sc1[2];
    #pragma unroll
    for (int mi = 0; mi < 2; mi++) {
        const int r0 = r_base + mi * 16;
        const float bg0 = s_ap[r0 * NP1];
        const float bg1 = s_ap[(r0 + 8) * NP1];
        sc0[mi] = (1.f - bg0) / fmaxf(fs[mi][0], 1e-6f);
        sc1[mi] = (1.f - bg1) / fmaxf(fs[mi][1], 1e-6f);
    }

    __syncthreads();                  // all warps done reading s_ap / s_B
    float* s_acc = s_ap;              // reuse ap region: 128*52*4 = 26624 <= 33280
    #pragma unroll
    for (int mi = 0; mi < 2; mi++) {
        const int r0 = r_base + mi * 16;
        #pragma unroll
        for (int ni = 0; ni < NI; ni++) {
            const int col = ni * 8 + 2 * tig;
            float2 v0, v1;
            v0.x = sc0[mi] * c[mi][ni][0];
            v0.y = sc0[mi] * c[mi][ni][1];
            v1.x = sc1[mi] * c[mi][ni][2];
            v1.y = sc1[mi] * c[mi][ni][3];
            *(float2*)(s_acc + r0 * ACC_STRIDE + col)       = v0;
            *(float2*)(s_acc + (r0 + 8) * ACC_STRIDE + col) = v1;
        }
    }
    __syncthreads();

    // ---- fully coalesced epilogue ----
    out[p0 + tid] = (float)aq[p0 + tid];

    const float4* sa4 = (const float4*)s_acc;
    {
        const float4* ia4 = (const float4*)(ia + (size_t)p0 * IDIM);
        float4* o4 = (float4*)(out + (size_t)NPIX + (size_t)p0 * IDIM);
        #pragma unroll
        for (int it = 0; it < PPB * IDIM / 4 / TPB; it++) {   // 8
            const int i  = tid + it * TPB;
            const int j  = i >> 3;
            const int d4 = i & 7;
            float4 v = ia4[i];
            float4 a = sa4[j * (ACC_STRIDE / 4) + d4];
            v.x += a.x; v.y += a.y; v.z += a.z; v.w += a.w;
            o4[i] = v;
        }
    }
    {
        const float4* mc4 = (const float4*)(mc + (size_t)p0 * MDIM);
        float4* o4 = (float4*)(out + (size_t)NPIX + (size_t)NPIX * IDIM + (size_t)p0 * MDIM);
        #pragma unroll
        for (int it = 0; it < PPB * MDIM / 4 / TPB; it++) {   // 4
            const int i  = tid + it * TPB;
            const int j  = i >> 2;
            const int d4 = i & 3;
            float4 v = mc4[i];
            float4 a = sa4[j * (ACC_STRIDE / 4) + (IDIM / 4) + d4];
            v.x += a.x; v.y += a.y; v.z += a.z; v.w += a.w;
            o4[i] = v;
        }
    }
}

// ---------------------------------------------------------------------------
extern "C" void kernel_launch(void* const* d_in, const int* in_sizes, int n_in,
                              void* d_out, int out_size) {
    const float* ia = (const float*)d_in[0];
    const float* mc = (const float*)d_in[1];
    const float* qf = (const float*)d_in[2];
    const float* ap = (const float*)d_in[3];
    const int*   aq = (const int*)  d_in[4];
    const float* Wi = (const float*)d_in[5];
    const float* bi = (const float*)d_in[6];
    const float* Wm = (const float*)d_in[7];
    const float* bm = (const float*)d_in[8];

    cudaFuncSetAttribute(entity_kernel,
                         cudaFuncAttributeMaxDynamicSharedMemorySize, SMEM_BYTES);

    qproj_kernel<<<NBT * NQ, 64>>>(qf, Wi, bi, Wm, bm);
    entity_kernel<<<NBLK, TPB, SMEM_BYTES>>>(ia, mc, ap, aq, (float*)d_out);
}